// round 12
// baseline (speedup 1.0000x reference)
#include <cuda_runtime.h>
#include <cuda_fp16.h>
#include <math.h>

#define NMAX 100000
#define EMAX 3200000

// ---------------- persistent device scratch (no runtime allocation) ----------------
// NOTE: g_deg relies on zero-initialized __device__ state on the FIRST call and is
// re-zeroed by final_k at the end of EVERY call (deterministic, same work each call).
__device__ int   g_csr_src[EMAX];    // src ids grouped by dst
__device__ int   g_deg[NMAX];        // in-degree (zeroed at end of each call)
__device__ int   g_rowptr[NMAX];     // CSR row starts
__device__ int   g_cur[NMAX];        // scatter cursors
__device__ int   g_bsum[128];        // scan block sums
__device__ __align__(16) __half2 g_h16[NMAX * 16];  // fp16 node features (64B/row)
__device__ float g_S[NMAX * 32];     // aggregation numerator (fp32)
__device__ float g_as[NMAX * 2];     // per-node source attention coeff (fp32)
__device__ float g_ad[NMAX * 2];     // per-node dest attention coeff (fp32)
__device__ float g_den[NMAX * 2];    // softmax denominator (2-head layers)
__device__ float g_den1[NMAX];       // softmax denominator (1-head layer)
__device__ int   g_is64;             // edge_index dtype flag

// in-degree histogram straight from edge_index (g_deg pre-zeroed by prior call)
__global__ void hist_k(const void* __restrict__ ei, int E) {
    int e = blockIdx.x * blockDim.x + threadIdx.x;
    if (e >= E) return;
    int d = g_is64 ? (int)((const long long*)ei)[E + e]
                   : ((const int*)ei)[E + e];
    atomicAdd(&g_deg[d], 1);
}

// ---------------- scan over degrees -> rowptr (block sums in g_bsum) ----------------
__global__ void scanA_k(int N) {
    __shared__ int sh[1024];
    const int tid = threadIdx.x;
    const int i = blockIdx.x * 1024 + tid;
    int v = (i < N) ? g_deg[i] : 0;
    sh[tid] = v;
    __syncthreads();
    for (int off = 1; off < 1024; off <<= 1) {
        int t = (tid >= off) ? sh[tid - off] : 0;
        __syncthreads();
        sh[tid] += t;
        __syncthreads();
    }
    if (i < N) g_rowptr[i] = sh[tid] - v;   // exclusive within block
    if (tid == 1023) g_bsum[blockIdx.x] = sh[tid];
}

// scanB fused in: every block redundantly scans the <=128 block sums in smem.
__global__ void scanC_k(int N, int nb) {
    __shared__ int so[128];
    const int tid = threadIdx.x;
    if (tid < 128) so[tid] = (tid < nb) ? g_bsum[tid] : 0;
    __syncthreads();
    for (int off = 1; off < 128; off <<= 1) {
        int t = (tid >= off && tid < 128) ? so[tid - off] : 0;
        __syncthreads();
        if (tid < 128) so[tid] += t;
        __syncthreads();
    }
    int i = blockIdx.x * blockDim.x + tid;
    if (i < N) {
        const int blk = i >> 10;
        const int off = (blk == 0) ? 0 : so[blk - 1];
        const int r = g_rowptr[i] + off;
        g_rowptr[i] = r;
        g_cur[i] = r;
    }
}

__global__ void scatter_k(const void* __restrict__ ei, int E) {
    int e = blockIdx.x * blockDim.x + threadIdx.x;
    if (e >= E) return;
    int s, d;
    if (g_is64) {
        const long long* p = (const long long*)ei;
        s = (int)p[e];
        d = (int)p[E + e];
    } else {
        const int* p = (const int*)ei;
        s = p[e];
        d = p[E + e];
    }
    int pos = atomicAdd(&g_cur[d], 1);
    g_csr_src[pos] = s;
}

// ---------------- node kernel: epilogue of prev layer (opt) + transform + att dots
// MODE 0: input = x, ALSO runs the edge-index dtype probe (launch #1, pre-hist).
// MODE 1: after layer1 (scale/1.05/elu/clip). MODE 2: after layer2.
// OH = heads of the NEW layer. Writes h as fp16 (64B rows) + fp32 as/ad.
template <int MODE, int OH>
__global__ void node_k(const float* __restrict__ xin,
                       const float* __restrict__ W,
                       const float* __restrict__ att_s,
                       const float* __restrict__ att_d,
                       const float* __restrict__ bias,
                       const float* __restrict__ ea,
                       const int* __restrict__ ei32,
                       int N) {
    __shared__ float sh[128 * 33];
    __shared__ float Wsh[1024];      // Wsh[i*32+o] = W[o][i]
    __shared__ float s_att[64];

    const int tid  = threadIdx.x;
    const int base = blockIdx.x * 128;
    const int count = min(128, N - base);

    if (MODE == 0 && blockIdx.x == 0 && tid == 0) {
        int acc = 0;
        for (int k = 0; k < 512; k++) acc |= ei32[2 * k + 1];
        g_is64 = (acc == 0) ? 1 : 0;
    }

    for (int idx = tid; idx < 1024; idx += 128) {
        int o = idx >> 5, i = idx & 31;
        Wsh[i * 32 + o] = W[idx];
    }
    if (tid < 32) { s_att[tid] = att_s[tid]; s_att[32 + tid] = att_d[tid]; }

    for (int idx = tid; idx < count * 32; idx += 128) {
        float v = (MODE == 0) ? xin[base * 32 + idx] : g_S[base * 32 + idx];
        sh[(idx >> 5) * 33 + (idx & 31)] = v;
    }
    __syncthreads();

    const int n = base + tid;
    if (n < N) {
        float* row = &sh[tid * 33];
        if (MODE != 0) {
            const float d0 = g_den[n * 2 + 0] + 1e-16f;
            const float d1 = g_den[n * 2 + 1] + 1e-16f;
            float sc = 1.f;
            if (MODE == 1) {
                float t = tanhf(ea[0]);
                sc = (t < 0.1f) ? 1.f : t;
                sc *= 1.05f;   // h + 0.05*detach(h) == 1.05*h
            }
#pragma unroll
            for (int i = 0; i < 32; i++) {
                float v = row[i] / (i < 16 ? d0 : d1) + bias[i];
                if (MODE == 1) v *= sc;
                v = (v > 0.f) ? v : expm1f(v);         // elu
                v = fminf(3.f, fmaxf(-3.f, v));        // clip
                row[i] = v;
            }
        }
        float acc[32];
#pragma unroll
        for (int o = 0; o < 32; o++) acc[o] = 0.f;
#pragma unroll
        for (int i = 0; i < 32; i++) {
            const float xv = row[i];
#pragma unroll
            for (int o = 0; o < 32; o++) acc[o] += xv * Wsh[i * 32 + o];
        }
        constexpr int CH = 32 / OH;
#pragma unroll
        for (int h = 0; h < OH; h++) {
            float as = 0.f, ad = 0.f;
#pragma unroll
            for (int c = 0; c < CH; c++) {
                as += acc[h * CH + c] * s_att[h * CH + c];
                ad += acc[h * CH + c] * s_att[32 + h * CH + c];
            }
            g_as[n * OH + h] = as;
            g_ad[n * OH + h] = ad;
        }
#pragma unroll
        for (int o = 0; o < 32; o++) row[o] = acc[o];
    }
    __syncthreads();
    // write fp16 h rows (16 half2 per node), coalesced
    for (int idx = tid; idx < count * 16; idx += 128) {
        const int r = idx >> 4, c2 = idx & 15;
        g_h16[(size_t)(base + r) * 16 + c2] =
            __floats2half2_rn(sh[r * 33 + 2 * c2], sh[r * 33 + 2 * c2 + 1]);
    }
}

// ---------------- warp-per-node aggregation: 8 edge-slots x 4 channel-lanes -------
// fp16 h (64B rows) lets one uint4 LDG per lane cover 8 channels, so a warp
// processes 8 edges/iteration (serial depth deg/8, MLP up to 16 with unroll 4).
// Flat per-lane loop, ZERO warp communication inside; shfl-ADD combine after.
template <int H>
__global__ void agg_warp_k(int N, float slope) {
    const int warp = (blockIdx.x * blockDim.x + threadIdx.x) >> 5;
    if (warp >= N) return;                 // uniform per warp
    const int lane  = threadIdx.x & 31;
    const int eslot = lane >> 2;           // 0..7
    const int j     = lane & 3;            // channel group (8 channels, 16B)
    const int head  = (H == 2) ? (j >> 1) : 0;

    const int beg = g_rowptr[warp];
    const int deg = g_deg[warp];
    const float adh = g_ad[warp * H + head];

    float acc[8];
#pragma unroll
    for (int c = 0; c < 8; c++) acc[c] = 0.f;
    float den = 0.f;

#pragma unroll 4
    for (int i = eslot; i < deg; i += 8) {
        const int s = __ldg(&g_csr_src[beg + i]);
        float l = __ldg(&g_as[s * H + head]) + adh;
        l = (l > 0.f) ? l : l * slope;
        const float ex = __expf(l);
        const uint4 raw = *reinterpret_cast<const uint4*>(&g_h16[(size_t)s * 16 + j * 4]);
        float2 f;
        f = __half22float2(*reinterpret_cast<const __half2*>(&raw.x));
        acc[0] += ex * f.x; acc[1] += ex * f.y;
        f = __half22float2(*reinterpret_cast<const __half2*>(&raw.y));
        acc[2] += ex * f.x; acc[3] += ex * f.y;
        f = __half22float2(*reinterpret_cast<const __half2*>(&raw.z));
        acc[4] += ex * f.x; acc[5] += ex * f.y;
        f = __half22float2(*reinterpret_cast<const __half2*>(&raw.w));
        acc[6] += ex * f.x; acc[7] += ex * f.y;
        den += ex;
    }
    // combine the 8 eslots: xor 4,8,16 keeps j (channels/head) fixed
#pragma unroll
    for (int k = 4; k < 32; k <<= 1) {
#pragma unroll
        for (int c = 0; c < 8; c++)
            acc[c] += __shfl_xor_sync(0xffffffffu, acc[c], k);
        den += __shfl_xor_sync(0xffffffffu, den, k);
    }

    if (eslot == 0) {                      // lanes 0..3 write their 8 channels
        *reinterpret_cast<float4*>(&g_S[(size_t)warp * 32 + j * 8]) =
            make_float4(acc[0], acc[1], acc[2], acc[3]);
        *reinterpret_cast<float4*>(&g_S[(size_t)warp * 32 + j * 8 + 4]) =
            make_float4(acc[4], acc[5], acc[6], acc[7]);
        if (H == 2) {
            if (j == 0) g_den[warp * 2 + 0] = den;   // j 0,1 accumulated head0
            if (j == 2) g_den[warp * 2 + 1] = den;   // j 2,3 accumulated head1
        } else {
            if (j == 0) g_den1[warp] = den;
        }
    }
}

// ---------------- final epilogue: normalize + bias; also re-zero g_deg ------------
__global__ void final_k(const float* __restrict__ b3, float* __restrict__ out, int N) {
    int idx = blockIdx.x * blockDim.x + threadIdx.x;
    if (idx < N * 32)
        out[idx] = g_S[idx] / (g_den1[idx >> 5] + 1e-16f) + b3[idx & 31];
    if (idx < N) g_deg[idx] = 0;   // invariant: g_deg zero at call exit
}

extern "C" void kernel_launch(void* const* d_in, const int* in_sizes, int n_in,
                              void* d_out, int out_size) {
    const float* x   = (const float*)d_in[0];
    const void*  ei  = d_in[1];
    const float* W1  = (const float*)d_in[2];
    const float* as1 = (const float*)d_in[3];
    const float* ad1 = (const float*)d_in[4];
    const float* b1  = (const float*)d_in[5];
    const float* ea1 = (const float*)d_in[6];
    const float* W2  = (const float*)d_in[7];
    const float* as2 = (const float*)d_in[8];
    const float* ad2 = (const float*)d_in[9];
    const float* b2  = (const float*)d_in[10];
    const float* W3  = (const float*)d_in[11];
    const float* as3 = (const float*)d_in[12];
    const float* ad3 = (const float*)d_in[13];
    const float* b3  = (const float*)d_in[14];
    float* out = (float*)d_out;

    const int N  = in_sizes[0] / 32;
    const int E  = in_sizes[1] / 2;
    const int nb = (N + 127) / 128;
    const int eb = (E + 255) / 256;
    const int wb = (int)(((long long)N * 32 + 255) / 256);
    const int sb = (N + 1023) / 1024;

    // #1: layer-1 node transform (CSR-independent) + dtype probe
    node_k<0, 2><<<nb, 128>>>(x, W1, as1, ad1, nullptr, nullptr, (const int*)ei, N);
    // #2-#5: CSR build (g_deg arrives zeroed from previous call / initial state)
    hist_k<<<eb, 256>>>(ei, E);
    scanA_k<<<sb, 1024>>>(N);
    scanC_k<<<(N + 255) / 256, 256>>>(N, sb);
    scatter_k<<<eb, 256>>>(ei, E);
    // #6: layer-1 aggregation
    agg_warp_k<2><<<wb, 256>>>(N, 0.01f);

    // ---- layer 2 (slope 0.2, H=2) ----
    node_k<1, 2><<<nb, 128>>>(nullptr, W2, as2, ad2, b1, ea1, nullptr, N);
    agg_warp_k<2><<<wb, 256>>>(N, 0.2f);

    // ---- layer 3 (slope 0.2, H=1) ----
    node_k<2, 1><<<nb, 128>>>(nullptr, W3, as3, ad3, b2, nullptr, nullptr, N);
    agg_warp_k<1><<<wb, 256>>>(N, 0.2f);

    // epilogue + re-zero g_deg for the next call
    final_k<<<(N * 32 + 255) / 256, 256>>>(b3, out, N);
}

// round 13
// speedup vs baseline: 1.0297x; 1.0297x over previous
#include <cuda_runtime.h>
#include <math.h>

#define NMAX 100000
#define EMAX 3200000

// ---------------- persistent device scratch (no runtime allocation) ----------------
// NOTE: g_deg relies on zero-initialized __device__ state on the FIRST call and is
// re-zeroed by final_k at the end of EVERY call (deterministic, same work each call).
__device__ int   g_csr_src[EMAX];    // src ids grouped by dst
__device__ int   g_deg[NMAX];        // in-degree (zeroed at end of each call)
__device__ int   g_rowptr[NMAX];     // CSR row starts
__device__ int   g_cur[NMAX];        // scatter cursors
__device__ int   g_bsum[128];        // scan block sums
__device__ float g_h[NMAX * 32];     // transformed node features of current layer
__device__ float g_S[NMAX * 32];     // aggregation numerator
__device__ float g_as[NMAX * 2];     // per-node source attention coeff
__device__ float g_ad[NMAX * 2];     // per-node dest attention coeff
__device__ float g_den[NMAX * 2];    // softmax denominator (2-head layers)
__device__ float g_den1[NMAX];       // softmax denominator (1-head layer)
__device__ int   g_is64;             // edge_index dtype flag

// ---- in-degree histogram straight from edge_index, 2 edges per thread ----
__global__ void hist_k(const void* __restrict__ ei, int E) {
    int t = blockIdx.x * blockDim.x + threadIdx.x;
    int e = t * 2;
    if (e >= E) return;
    if (g_is64) {
        const ulonglong2 p = *reinterpret_cast<const ulonglong2*>(
            (const long long*)ei + E + e);
        atomicAdd(&g_deg[(int)p.x], 1);
        atomicAdd(&g_deg[(int)p.y], 1);
    } else {
        const int2 p = *reinterpret_cast<const int2*>((const int*)ei + E + e);
        atomicAdd(&g_deg[p.x], 1);
        atomicAdd(&g_deg[p.y], 1);
    }
}

// ---------------- scan over degrees -> rowptr (warp-shuffle based) ----------------
__global__ void scanA_k(int N) {
    __shared__ int wsum[32];
    const int tid  = threadIdx.x;
    const int lane = tid & 31;
    const int wid  = tid >> 5;
    const int i = blockIdx.x * 1024 + tid;
    const int v = (i < N) ? g_deg[i] : 0;

    // warp inclusive scan
    int s = v;
#pragma unroll
    for (int k = 1; k < 32; k <<= 1) {
        int t = __shfl_up_sync(0xffffffffu, s, k);
        if (lane >= k) s += t;
    }
    if (lane == 31) wsum[wid] = s;
    __syncthreads();
    if (wid == 0) {
        int w = wsum[lane];
#pragma unroll
        for (int k = 1; k < 32; k <<= 1) {
            int t = __shfl_up_sync(0xffffffffu, w, k);
            if (lane >= k) w += t;
        }
        wsum[lane] = w;
    }
    __syncthreads();
    const int add = (wid > 0) ? wsum[wid - 1] : 0;
    if (i < N) g_rowptr[i] = s + add - v;           // exclusive within block
    if (tid == 1023) g_bsum[blockIdx.x] = s + add;  // block total
}

// apply block offsets; block-sum scan done redundantly per block by warp 0
__global__ void scanC_k(int N, int nb) {
    __shared__ int so[128];
    const int tid = threadIdx.x;
    if (tid < 32) {
        // scan 128 block sums with one warp: 4 values per lane, sequential-of-shfl
        int a0 = (tid < nb)       ? g_bsum[tid]       : 0;
        int a1 = (tid + 32 < nb)  ? g_bsum[tid + 32]  : 0;
        int a2 = (tid + 64 < nb)  ? g_bsum[tid + 64]  : 0;
        int a3 = (tid + 96 < nb)  ? g_bsum[tid + 96]  : 0;
        // inclusive scan of each 32-chunk
        int s0 = a0, s1 = a1, s2 = a2, s3 = a3;
#pragma unroll
        for (int k = 1; k < 32; k <<= 1) {
            int t0 = __shfl_up_sync(0xffffffffu, s0, k);
            int t1 = __shfl_up_sync(0xffffffffu, s1, k);
            int t2 = __shfl_up_sync(0xffffffffu, s2, k);
            int t3 = __shfl_up_sync(0xffffffffu, s3, k);
            if (tid >= k) { s0 += t0; s1 += t1; s2 += t2; s3 += t3; }
        }
        const int tot0 = __shfl_sync(0xffffffffu, s0, 31);
        const int tot1 = __shfl_sync(0xffffffffu, s1, 31);
        const int tot2 = __shfl_sync(0xffffffffu, s2, 31);
        so[tid]      = s0;
        so[tid + 32] = s1 + tot0;
        so[tid + 64] = s2 + tot0 + tot1;
        so[tid + 96] = s3 + tot0 + tot1 + tot2;
    }
    __syncthreads();
    int i = blockIdx.x * blockDim.x + tid;
    if (i < N) {
        const int blk = i >> 10;
        const int off = (blk == 0) ? 0 : so[blk - 1];
        const int r = g_rowptr[i] + off;
        g_rowptr[i] = r;
        g_cur[i] = r;
    }
}

// ---- scatter src ids into CSR order, 2 edges per thread ----
__global__ void scatter_k(const void* __restrict__ ei, int E) {
    int t = blockIdx.x * blockDim.x + threadIdx.x;
    int e = t * 2;
    if (e >= E) return;
    int s0, d0, s1, d1;
    if (g_is64) {
        const ulonglong2 ps = *reinterpret_cast<const ulonglong2*>(
            (const long long*)ei + e);
        const ulonglong2 pd = *reinterpret_cast<const ulonglong2*>(
            (const long long*)ei + E + e);
        s0 = (int)ps.x; s1 = (int)ps.y;
        d0 = (int)pd.x; d1 = (int)pd.y;
    } else {
        const int2 ps = *reinterpret_cast<const int2*>((const int*)ei + e);
        const int2 pd = *reinterpret_cast<const int2*>((const int*)ei + E + e);
        s0 = ps.x; s1 = ps.y;
        d0 = pd.x; d1 = pd.y;
    }
    g_csr_src[atomicAdd(&g_cur[d0], 1)] = s0;
    g_csr_src[atomicAdd(&g_cur[d1], 1)] = s1;
}

// ---------------- node kernel: epilogue of prev layer (opt) + transform + att dots
// MODE 0: input = x, ALSO runs the edge-index dtype probe (launch #1, pre-hist).
// MODE 1: after layer1 (scale/1.05/elu/clip). MODE 2: after layer2.
// OH = heads of the NEW layer being prepared.
template <int MODE, int OH>
__global__ void node_k(const float* __restrict__ xin,
                       const float* __restrict__ W,
                       const float* __restrict__ att_s,
                       const float* __restrict__ att_d,
                       const float* __restrict__ bias,
                       const float* __restrict__ ea,
                       const int* __restrict__ ei32,
                       int N) {
    __shared__ float sh[128 * 33];
    __shared__ float Wsh[1024];      // Wsh[i*32+o] = W[o][i]
    __shared__ float s_att[64];

    const int tid  = threadIdx.x;
    const int base = blockIdx.x * 128;
    const int count = min(128, N - base);

    if (MODE == 0 && blockIdx.x == 0 && tid == 0) {
        int acc = 0;
        for (int k = 0; k < 512; k++) acc |= ei32[2 * k + 1];
        g_is64 = (acc == 0) ? 1 : 0;
    }

    for (int idx = tid; idx < 1024; idx += 128) {
        int o = idx >> 5, i = idx & 31;
        Wsh[i * 32 + o] = W[idx];
    }
    if (tid < 32) { s_att[tid] = att_s[tid]; s_att[32 + tid] = att_d[tid]; }

    for (int idx = tid; idx < count * 32; idx += 128) {
        float v = (MODE == 0) ? xin[base * 32 + idx] : g_S[base * 32 + idx];
        sh[(idx >> 5) * 33 + (idx & 31)] = v;
    }
    __syncthreads();

    const int n = base + tid;
    if (n < N) {
        float* row = &sh[tid * 33];
        if (MODE != 0) {
            const float d0 = g_den[n * 2 + 0] + 1e-16f;
            const float d1 = g_den[n * 2 + 1] + 1e-16f;
            float sc = 1.f;
            if (MODE == 1) {
                float t = tanhf(ea[0]);
                sc = (t < 0.1f) ? 1.f : t;
                sc *= 1.05f;   // h + 0.05*detach(h) == 1.05*h
            }
#pragma unroll
            for (int i = 0; i < 32; i++) {
                float v = row[i] / (i < 16 ? d0 : d1) + bias[i];
                if (MODE == 1) v *= sc;
                v = (v > 0.f) ? v : expm1f(v);         // elu
                v = fminf(3.f, fmaxf(-3.f, v));        // clip
                row[i] = v;
            }
        }
        float acc[32];
#pragma unroll
        for (int o = 0; o < 32; o++) acc[o] = 0.f;
#pragma unroll
        for (int i = 0; i < 32; i++) {
            const float xv = row[i];
#pragma unroll
            for (int o = 0; o < 32; o++) acc[o] += xv * Wsh[i * 32 + o];
        }
        constexpr int CH = 32 / OH;
#pragma unroll
        for (int h = 0; h < OH; h++) {
            float as = 0.f, ad = 0.f;
#pragma unroll
            for (int c = 0; c < CH; c++) {
                as += acc[h * CH + c] * s_att[h * CH + c];
                ad += acc[h * CH + c] * s_att[32 + h * CH + c];
            }
            g_as[n * OH + h] = as;
            g_ad[n * OH + h] = ad;
        }
#pragma unroll
        for (int o = 0; o < 32; o++) row[o] = acc[o];
    }
    __syncthreads();
    for (int idx = tid; idx < count * 32; idx += 128)
        g_h[base * 32 + idx] = sh[(idx >> 5) * 33 + (idx & 31)];
}

// ---------------- SINGLE-PASS warp-per-node aggregation (champion form, UNCHANGED) -
// 4 edge-slots x 8 channel-lanes; flat per-lane loop, zero warp communication
// inside the loop. Per edge: as gather, exp, 16B h gather, FMA. shfl-ADD combine.
template <int H>
__global__ void agg_warp_k(int N, float slope) {
    const int warp = (blockIdx.x * blockDim.x + threadIdx.x) >> 5;
    if (warp >= N) return;                 // uniform per warp
    const int lane  = threadIdx.x & 31;
    const int eslot = lane >> 3;           // 0..3
    const int j     = lane & 7;            // channel group (16B each)
    const int head  = (H == 2) ? (j >> 2) : 0;

    const int beg = g_rowptr[warp];
    const int deg = g_deg[warp];
    const float adh = g_ad[warp * H + head];

    float4 acc = make_float4(0.f, 0.f, 0.f, 0.f);
    float den = 0.f;
#pragma unroll 4
    for (int i = eslot; i < deg; i += 4) {
        const int s = __ldg(&g_csr_src[beg + i]);
        float l = __ldg(&g_as[s * H + head]) + adh;
        l = (l > 0.f) ? l : l * slope;
        const float ex = __expf(l);
        const float4 hv = *reinterpret_cast<const float4*>(&g_h[(size_t)s * 32 + j * 4]);
        acc.x += ex * hv.x;
        acc.y += ex * hv.y;
        acc.z += ex * hv.z;
        acc.w += ex * hv.w;
        den += ex;
    }
    // combine eslots (lanes differing in bits 3,4 share j and head)
#pragma unroll
    for (int k = 8; k < 32; k <<= 1) {
        acc.x += __shfl_xor_sync(0xffffffffu, acc.x, k);
        acc.y += __shfl_xor_sync(0xffffffffu, acc.y, k);
        acc.z += __shfl_xor_sync(0xffffffffu, acc.z, k);
        acc.w += __shfl_xor_sync(0xffffffffu, acc.w, k);
        den   += __shfl_xor_sync(0xffffffffu, den, k);
    }

    if (eslot == 0) {
        *reinterpret_cast<float4*>(&g_S[(size_t)warp * 32 + j * 4]) = acc;
        if (H == 2) {
            if (j == 0) g_den[warp * 2 + 0] = den;
            if (j == 4) g_den[warp * 2 + 1] = den;
        } else {
            if (j == 0) g_den1[warp] = den;
        }
    }
}

// ---------------- final epilogue: normalize + bias; also re-zero g_deg ------------
__global__ void final_k(const float* __restrict__ b3, float* __restrict__ out, int N) {
    int idx = blockIdx.x * blockDim.x + threadIdx.x;
    if (idx < N * 32)
        out[idx] = g_S[idx] / (g_den1[idx >> 5] + 1e-16f) + b3[idx & 31];
    if (idx < N) g_deg[idx] = 0;   // invariant: g_deg zero at call exit
}

extern "C" void kernel_launch(void* const* d_in, const int* in_sizes, int n_in,
                              void* d_out, int out_size) {
    const float* x   = (const float*)d_in[0];
    const void*  ei  = d_in[1];
    const float* W1  = (const float*)d_in[2];
    const float* as1 = (const float*)d_in[3];
    const float* ad1 = (const float*)d_in[4];
    const float* b1  = (const float*)d_in[5];
    const float* ea1 = (const float*)d_in[6];
    const float* W2  = (const float*)d_in[7];
    const float* as2 = (const float*)d_in[8];
    const float* ad2 = (const float*)d_in[9];
    const float* b2  = (const float*)d_in[10];
    const float* W3  = (const float*)d_in[11];
    const float* as3 = (const float*)d_in[12];
    const float* ad3 = (const float*)d_in[13];
    const float* b3  = (const float*)d_in[14];
    float* out = (float*)d_out;

    const int N  = in_sizes[0] / 32;
    const int E  = in_sizes[1] / 2;
    const int nb = (N + 127) / 128;
    const int e2 = (E / 2 + 255) / 256;    // 2 edges per thread
    const int wb = (int)(((long long)N * 32 + 255) / 256);
    const int sb = (N + 1023) / 1024;

    // #1: layer-1 node transform (CSR-independent) + dtype probe
    node_k<0, 2><<<nb, 128>>>(x, W1, as1, ad1, nullptr, nullptr, (const int*)ei, N);
    // #2-#5: CSR build (g_deg arrives zeroed from previous call / initial state)
    hist_k<<<e2, 256>>>(ei, E);
    scanA_k<<<sb, 1024>>>(N);
    scanC_k<<<(N + 255) / 256, 256>>>(N, sb);
    scatter_k<<<e2, 256>>>(ei, E);
    // #6: layer-1 aggregation
    agg_warp_k<2><<<wb, 256>>>(N, 0.01f);

    // ---- layer 2 (slope 0.2, H=2) ----
    node_k<1, 2><<<nb, 128>>>(nullptr, W2, as2, ad2, b1, ea1, nullptr, N);
    agg_warp_k<2><<<wb, 256>>>(N, 0.2f);

    // ---- layer 3 (slope 0.2, H=1) ----
    node_k<2, 1><<<nb, 128>>>(nullptr, W3, as3, ad3, b2, nullptr, nullptr, N);
    agg_warp_k<1><<<wb, 256>>>(N, 0.2f);

    // epilogue + re-zero g_deg for the next call
    final_k<<<(N * 32 + 255) / 256, 256>>>(b3, out, N);
}